// round 2
// baseline (speedup 1.0000x reference)
#include <cuda_runtime.h>
#include <cstdint>
#include <cstddef>

#define SEQ 4096
#define EMB 200
#define HID 256
#define G3  768

#define HID_OUT_OFF (SEQ*EMB)                 /* 819200  */
#define LAST_OFF    (HID_OUT_OFF + SEQ*2*HID) /* 2916352 */

// Scratch: precomputed input-side gates. gi[dir][t][row]
// rows 0..511 (r,z) have b_ih + b_hh folded in; rows 512..767 (n) have only b_ih.
__device__ float g_gi[2][SEQ][G3];

// ---------------------------------------------------------------------------
// Phase 1a: embeddings output = emb_weight[utterance]  (float4 copy)
// ---------------------------------------------------------------------------
__global__ void embed_copy_kernel(const int* __restrict__ tok,
                                  const float* __restrict__ emb,
                                  float4* __restrict__ out4) {
    int i = blockIdx.x * 256 + threadIdx.x;
    if (i < SEQ * 50) {
        int t  = i / 50;
        int k4 = i - t * 50;
        const float4* row = (const float4*)(emb + (size_t)tok[t] * EMB);
        out4[i] = row[k4];
    }
}

// ---------------------------------------------------------------------------
// Phase 1b: gi GEMM (unchanged from R1 — not the bottleneck)
// ---------------------------------------------------------------------------
#define TT 64
#define RT 64
#define KP 204
#define GI_SMEM ((TT + RT) * KP * 4)

extern "C" __global__ void __launch_bounds__(256)
gi_gemm_kernel(const int* __restrict__ tok,
               const float* __restrict__ emb,
               const float* __restrict__ w_ih1, const float* __restrict__ w_ih2,
               const float* __restrict__ b_ih1, const float* __restrict__ b_ih2,
               const float* __restrict__ b_hh1, const float* __restrict__ b_hh2) {
    extern __shared__ float sm[];
    float* xs = sm;
    float* ws = sm + TT * KP;

    int dir = blockIdx.z;
    const float* w_ih = dir ? w_ih2 : w_ih1;
    const float* b_ih = dir ? b_ih2 : b_ih1;
    const float* b_hh = dir ? b_hh2 : b_hh1;
    float* gi = &g_gi[dir][0][0];

    int t0 = blockIdx.x * TT;
    int r0 = blockIdx.y * RT;
    int tid = threadIdx.x;

    for (int i = tid; i < TT * 50; i += 256) {
        int tt = i / 50, k4 = i - tt * 50;
        float4 v = ((const float4*)(emb + (size_t)tok[t0 + tt] * EMB))[k4];
        *(float4*)&xs[tt * KP + k4 * 4] = v;
    }
    for (int i = tid; i < RT * 50; i += 256) {
        int rr = i / 50, k4 = i - rr * 50;
        float4 v = ((const float4*)(w_ih + (size_t)(r0 + rr) * EMB))[k4];
        *(float4*)&ws[rr * KP + k4 * 4] = v;
    }
    __syncthreads();

    int tx = tid & 15, ty = tid >> 4;
    int tt0 = ty * 4;

    float acc[4][4];
#pragma unroll
    for (int a = 0; a < 4; a++)
#pragma unroll
        for (int b = 0; b < 4; b++) acc[a][b] = 0.f;

#pragma unroll 2
    for (int k = 0; k < EMB; k += 4) {
        float4 xv[4], wv[4];
#pragma unroll
        for (int a = 0; a < 4; a++) xv[a] = *(const float4*)&xs[(tt0 + a) * KP + k];
#pragma unroll
        for (int b = 0; b < 4; b++) wv[b] = *(const float4*)&ws[(tx + 16 * b) * KP + k];
#pragma unroll
        for (int a = 0; a < 4; a++)
#pragma unroll
            for (int b = 0; b < 4; b++) {
                acc[a][b] = fmaf(xv[a].x, wv[b].x, acc[a][b]);
                acc[a][b] = fmaf(xv[a].y, wv[b].y, acc[a][b]);
                acc[a][b] = fmaf(xv[a].z, wv[b].z, acc[a][b]);
                acc[a][b] = fmaf(xv[a].w, wv[b].w, acc[a][b]);
            }
    }

#pragma unroll
    for (int b = 0; b < 4; b++) {
        int row = r0 + tx + 16 * b;
        float bias = b_ih[row] + (row < 512 ? b_hh[row] : 0.f);
#pragma unroll
        for (int a = 0; a < 4; a++) {
            int t = t0 + tt0 + a;
            gi[(size_t)t * G3 + row] = acc[a][b] + bias;
        }
    }
}

// ---------------------------------------------------------------------------
// Phase 2: sequential biGRU recurrence (rewritten).
//
// 2 clusters of 8 CTAs (one/direction), 256 threads/CTA.
// Warp wid owns h-indices jbase..jbase+3 (jbase = crank*32 + wid*4).
// Each warp = 4 groups of 8 lanes; group g owns h-index jbase+g, computing its
// 3 gate-rows (r,z,n). Lane (g,m) holds 32 contiguous h-columns [32m,32m+32)
// of those 3 rows, packed as 16 x f32x2. Matvec = 48 FFMA2/thread; reduce =
// 3 rows x 3 butterfly stages over 8 lanes; results land on lane m==0.
//
// Sync: DSMEM stores of new h + per-warp mbarrier arrive (release.cluster) on
// every CTA's parity-ping-pong "full" barrier (count 64 = 8 CTA x 8 warps);
// consumers try_wait.parity.acquire.cluster. No barrier.cluster in the loop.
// ---------------------------------------------------------------------------
__device__ __forceinline__ float sigf(float x) { return 1.f / (1.f + __expf(-x)); }
__device__ __forceinline__ float tanhfast(float x) { return 2.f / (1.f + __expf(-2.f * x)) - 1.f; }

#define FFMA2(d, a, b) \
    asm("fma.rn.f32x2 %0, %1, %2, %0;" : "+l"(d) : "l"(a), "l"(b))

extern "C" __global__ void __launch_bounds__(256, 1) __cluster_dims__(8, 1, 1)
gru_rec_kernel(const float* __restrict__ w_hh1, const float* __restrict__ w_hh2,
               const float* __restrict__ b_hh1, const float* __restrict__ b_hh2,
               const float* __restrict__ h01,   const float* __restrict__ h02,
               float* __restrict__ out) {
    __shared__ float hbuf[2][HID];
    __shared__ unsigned long long mbar[2];   // full[parity]

    unsigned crank;
    asm("mov.u32 %0, %%cluster_ctarank;" : "=r"(crank));
    int dir = (blockIdx.x >= 8) ? 1 : 0;
    const float* w_hh = dir ? w_hh2 : w_hh1;
    const float* b_hh = dir ? b_hh2 : b_hh1;
    const float* h0   = dir ? h02 : h01;
    const float* gi_base = &g_gi[dir][0][0];

    int tid  = threadIdx.x;
    int wid  = tid >> 5;
    int lane = tid & 31;
    int g    = lane >> 3;            // group within warp (h-index offset)
    int m    = lane & 7;             // lane within group (column chunk)
    int jbase = (int)crank * 32 + wid * 4;
    int j    = jbase + g;            // this group's h index

    // --- init barriers + seed hbuf[0] ---
    if (tid == 0) {
        asm volatile("mbarrier.init.shared.b64 [%0], 64;" ::
                     "r"((unsigned)__cvta_generic_to_shared(&mbar[0])) : "memory");
        asm volatile("mbarrier.init.shared.b64 [%0], 64;" ::
                     "r"((unsigned)__cvta_generic_to_shared(&mbar[1])) : "memory");
    }
    if (tid < HID) hbuf[0][tid] = h0[tid];
    __syncthreads();
    asm volatile("barrier.cluster.arrive.aligned;" ::: "memory");
    asm volatile("barrier.cluster.wait.aligned;"   ::: "memory");

    // --- register-resident weights: 3 rows x 32 cols, packed as f32x2 ---
    unsigned long long w0[16], w1[16], w2[16];
    {
        const unsigned long long* r0p = (const unsigned long long*)(w_hh + (size_t)(      j) * HID + 32 * m);
        const unsigned long long* r1p = (const unsigned long long*)(w_hh + (size_t)(256 + j) * HID + 32 * m);
        const unsigned long long* r2p = (const unsigned long long*)(w_hh + (size_t)(512 + j) * HID + 32 * m);
#pragma unroll
        for (int c = 0; c < 16; c++) { w0[c] = r0p[c]; w1[c] = r1p[c]; w2[c] = r2p[c]; }
    }

    // --- register-resident h chunk: 32 contiguous values as 16 x f32x2 ---
    unsigned long long hpk[16];
    {
        const unsigned long long* hp = (const unsigned long long*)(h0 + 32 * m);
#pragma unroll
        for (int c = 0; c < 16; c++) hpk[c] = hp[c];
    }

    float bhn = (m == 0) ? b_hh[512 + j] : 0.f;

    // --- precompute remote addresses (mapa once) ---
    unsigned hb_local = (unsigned)__cvta_generic_to_shared(&hbuf[0][0]);
    unsigned mb_local = (unsigned)__cvta_generic_to_shared(&mbar[0]);
    unsigned rem_h[8], rem_mb[8];
#pragma unroll
    for (int rk = 0; rk < 8; rk++) {
        asm("mapa.shared::cluster.u32 %0, %1, %2;" : "=r"(rem_h[rk])  : "r"(hb_local + (unsigned)j * 4u), "r"(rk));
        asm("mapa.shared::cluster.u32 %0, %1, %2;" : "=r"(rem_mb[rk]) : "r"(mb_local), "r"(rk));
    }

    // --- prefetch gi for step 0 ---
    int t0i = dir ? (SEQ - 1) : 0;
    float girN = 0.f, gizN = 0.f, ginN = 0.f;
    if (m == 0) {
        const float* gi = gi_base + (size_t)t0i * G3;
        girN = __ldg(gi + j);
        gizN = __ldg(gi + 256 + j);
        ginN = __ldg(gi + 512 + j);
    }

#pragma unroll 1
    for (int s = 0; s < SEQ; s++) {
        int t = dir ? (SEQ - 1 - s) : s;
        float girC = girN, gizC = gizN, ginC = ginN;

        // old h for this j (small LDS, issued early)
        float hold = 0.f;
        if (m == 0) hold = hbuf[s & 1][j];

        // prefetch gi for next step (independent of h — fully hideable)
        if (m == 0 && s + 1 < SEQ) {
            int tn = dir ? (SEQ - 2 - s) : (s + 1);
            const float* gi = gi_base + (size_t)tn * G3;
            girN = __ldg(gi + j);
            gizN = __ldg(gi + 256 + j);
            ginN = __ldg(gi + 512 + j);
        }

        // matvec: 48 packed FMAs
        unsigned long long a0 = 0ull, a1 = 0ull, a2 = 0ull;
#pragma unroll
        for (int c = 0; c < 16; c++) {
            unsigned long long hv = hpk[c];
            FFMA2(a0, w0[c], hv);
            FFMA2(a1, w1[c], hv);
            FFMA2(a2, w2[c], hv);
        }
        float ar, az, an;
        {
            float x, y;
            asm("mov.b64 {%0, %1}, %2;" : "=f"(x), "=f"(y) : "l"(a0)); ar = x + y;
            asm("mov.b64 {%0, %1}, %2;" : "=f"(x), "=f"(y) : "l"(a1)); az = x + y;
            asm("mov.b64 {%0, %1}, %2;" : "=f"(x), "=f"(y) : "l"(a2)); an = x + y;
        }
        // butterfly over the 8 lanes of this group
#pragma unroll
        for (int d = 4; d >= 1; d >>= 1) {
            ar += __shfl_xor_sync(0xffffffffu, ar, d);
            az += __shfl_xor_sync(0xffffffffu, az, d);
            an += __shfl_xor_sync(0xffffffffu, an, d);
        }

        int b = (s + 1) & 1;
        if (m == 0) {
            float r  = sigf(girC + ar);              // b_hh_r folded into gi
            float z  = sigf(gizC + az);              // b_hh_z folded into gi
            float n  = tanhfast(ginC + r * (an + bhn));
            float hn = n + z * (hold - n);

            out[HID_OUT_OFF + (size_t)t * 512 + dir * HID + j] = hn;
            if (s == SEQ - 1) out[LAST_OFF + dir * HID + j] = hn;

            if (s < SEQ - 1) {
                unsigned off = (unsigned)b * (HID * 4u);
#pragma unroll
                for (int rk = 0; rk < 8; rk++) {
                    asm volatile("st.shared::cluster.f32 [%0], %1;" ::
                                 "r"(rem_h[rk] + off), "f"(hn) : "memory");
                }
            }
        }

        if (s < SEQ - 1) {
            __syncwarp();
            if (lane == 0) {
                unsigned off = (unsigned)b * 8u;
#pragma unroll
                for (int rk = 0; rk < 8; rk++) {
                    asm volatile("mbarrier.arrive.release.cluster.shared::cluster.b64 _, [%0];" ::
                                 "r"(rem_mb[rk] + off) : "memory");
                }
            }

            // wait for all 64 warp-arrivals of this step, then reload h chunk
            unsigned mba = mb_local + (unsigned)b * 8u;
            unsigned par = (unsigned)((s >> 1) & 1);
            unsigned done;
            asm volatile(
                "{\n\t.reg .pred p;\n\t"
                "mbarrier.try_wait.parity.acquire.cluster.shared::cta.b64 p, [%1], %2;\n\t"
                "selp.b32 %0, 1, 0, p;\n\t}"
                : "=r"(done) : "r"(mba), "r"(par) : "memory");
            while (!done) {
                asm volatile(
                    "{\n\t.reg .pred p;\n\t"
                    "mbarrier.try_wait.parity.acquire.cluster.shared::cta.b64 p, [%1], %2, 0x989680;\n\t"
                    "selp.b32 %0, 1, 0, p;\n\t}"
                    : "=r"(done) : "r"(mba), "r"(par) : "memory");
            }

            const ulonglong2* hp = (const ulonglong2*)&hbuf[b][32 * m];
#pragma unroll
            for (int c = 0; c < 8; c++) {
                ulonglong2 v = hp[c];
                hpk[2 * c]     = v.x;
                hpk[2 * c + 1] = v.y;
            }
        }
    }
}

// ---------------------------------------------------------------------------
// Launcher
// ---------------------------------------------------------------------------
extern "C" void kernel_launch(void* const* d_in, const int* in_sizes, int n_in,
                              void* d_out, int out_size) {
    const int*   tok     = (const int*)  d_in[0];
    const float* hidden  = (const float*)d_in[1];
    const float* hidden2 = (const float*)d_in[2];
    const float* emb     = (const float*)d_in[3];
    const float* w_ih1   = (const float*)d_in[4];
    const float* w_hh1   = (const float*)d_in[5];
    const float* b_ih1   = (const float*)d_in[6];
    const float* b_hh1   = (const float*)d_in[7];
    const float* w_ih2   = (const float*)d_in[8];
    const float* w_hh2   = (const float*)d_in[9];
    const float* b_ih2   = (const float*)d_in[10];
    const float* b_hh2   = (const float*)d_in[11];
    float* out = (float*)d_out;

    embed_copy_kernel<<<(SEQ * 50 + 255) / 256, 256>>>(tok, emb, (float4*)out);

    cudaFuncSetAttribute(gi_gemm_kernel,
                         cudaFuncAttributeMaxDynamicSharedMemorySize, GI_SMEM);
    gi_gemm_kernel<<<dim3(SEQ / TT, G3 / RT, 2), 256, GI_SMEM>>>(
        tok, emb, w_ih1, w_ih2, b_ih1, b_ih2, b_hh1, b_hh2);

    gru_rec_kernel<<<16, 256>>>(w_hh1, w_hh2, b_hh1, b_hh2, hidden, hidden2, out);
}